// round 7
// baseline (speedup 1.0000x reference)
#include <cuda_runtime.h>

#define NN 10000
#define EE 160000
#define GG 64
#define HH 32
#define WIDTH 64   // ELL width; degree ~ Binomial(160k, 1e-4), P(>=64) ~ 1e-20

// ---- scratch (device globals; referenced ONLY in device code) ----
__device__ float  d_deg[NN];            // 1 + sum of incoming edge weights
__device__ int    d_count[NN];          // per-dst edge count / ELL fill cursor
__device__ float2 d_ell[NN * WIDTH];    // after k_norm: {src as int bits, full norm}; padded slots {0,0}
__device__ float  d_xt[NN * GG];        // x transposed (N, G)
__device__ float  d_zt[NN * GG];        // layer-1 output transposed
__device__ float  d_ot[NN * GG];        // layer-2 output transposed

// ---- K_A: fused init (deg=1, count=0) + transpose x (G,N) -> (N,G) ----
__global__ void k_prep(const float* __restrict__ x) {
    int flat = (blockIdx.y * gridDim.x + blockIdx.x) * 1024 + threadIdx.y * 32 + threadIdx.x;
    if (flat < NN) { d_deg[flat] = 1.0f; d_count[flat] = 0; }

    __shared__ float t[32][33];
    int n0 = blockIdx.x * 32, g0 = blockIdx.y * 32;
    int tx = threadIdx.x, ty = threadIdx.y;
    int n = n0 + tx, g = g0 + ty;
    if (n < NN) t[ty][tx] = x[g * NN + n];
    __syncthreads();
    n = n0 + ty; g = g0 + tx;
    if (n < NN) d_xt[n * GG + g] = t[tx][ty];
}

// ---- K_B: single edge pass: ELL build + degree accumulate (2 edges/thread) ----
__global__ void k_build(const int* __restrict__ ei, const float* __restrict__ w) {
    int i = blockIdx.x * blockDim.x + threadIdx.x;
    if (i < EE / 2) {
        int2   s2 = ((const int2*)ei)[i];            // src pair
        int2   d2 = ((const int2*)ei)[EE / 2 + i];   // dst pair (dst base = ei+EE)
        float2 w2 = ((const float2*)w)[i];

        int p0 = atomicAdd(&d_count[d2.x], 1);
        if (p0 < WIDTH) d_ell[d2.x * WIDTH + p0] = make_float2(__int_as_float(s2.x), w2.x);
        atomicAdd(&d_deg[d2.x], w2.x);

        int p1 = atomicAdd(&d_count[d2.y], 1);
        if (p1 < WIDTH) d_ell[d2.y * WIDTH + p1] = make_float2(__int_as_float(s2.y), w2.y);
        atomicAdd(&d_deg[d2.y], w2.y);
    }
}

// ---- K_C: pre-normalize ELL entries: w -> dinv[src]*w*dinv[dst] ----
__global__ void k_norm() {
    int row = blockIdx.x * 4 + (threadIdx.x >> 6);
    int j   = threadIdx.x & 63;
    if (row < NN && j < d_count[row]) {
        float2 p = d_ell[row * WIDTH + j];
        int s = __float_as_int(p.x);
        d_ell[row * WIDTH + j].y = p.y * rsqrtf(d_deg[s]) * rsqrtf(d_deg[row]);
    }
}

// ---- SpMV over pre-normalized ELL, warp-per-row, 2 replicas/lane ----
// 16-edge chunks: 8x LDG.128 metadata (float4 = TWO float2 edges) then 16
// independent gathers front-batched before the FMA block. Padded slots are
// {0,0} (BSS zero-init; every call rewrites only slots [0,count)) => zero
// contribution, no tail logic needed.
template <int LAYER>
__global__ void k_spmv(const float* __restrict__ Wa, const float* __restrict__ ba,
                       const float* __restrict__ Wb, const float* __restrict__ b2) {
    __shared__ float sW1[HH], sB1[HH], sW2[HH];
    if (LAYER == 1) {
        if (threadIdx.x < HH) {
            sW1[threadIdx.x] = Wa[threadIdx.x];
            sB1[threadIdx.x] = ba[threadIdx.x];
            sW2[threadIdx.x] = Wb[threadIdx.x];
        }
        __syncthreads();
    }

    int row  = (blockIdx.x * blockDim.x + threadIdx.x) >> 5;   // grid = exactly NN warps
    int lane = threadIdx.x & 31;
    const float2* in2 = (const float2*)(LAYER == 1 ? d_xt : d_zt);
    float2*       ou2 = (float2*)      (LAYER == 1 ? d_zt : d_ot);

    float sn = 1.0f / d_deg[row];             // self-loop norm = dinv^2
    float2 xs = in2[row * 32 + lane];
    float2 acc = make_float2(sn * xs.x, sn * xs.y);

    int cnt = min(d_count[row], WIDTH);
    const float4* ell4 = (const float4*)&d_ell[row * WIDTH];
    for (int base = 0; base < cnt; base += 16) {
        int q = base >> 1;                    // float4 index: 2 edges per float4
        float4 e0 = ell4[q + 0];
        float4 e1 = ell4[q + 1];
        float4 e2 = ell4[q + 2];
        float4 e3 = ell4[q + 3];
        float4 e4 = ell4[q + 4];
        float4 e5 = ell4[q + 5];
        float4 e6 = ell4[q + 6];
        float4 e7 = ell4[q + 7];
        // 16 independent gathers, front-batched (no consumer until FMA block)
        float2 v0  = in2[__float_as_int(e0.x) * 32 + lane];
        float2 v1  = in2[__float_as_int(e0.z) * 32 + lane];
        float2 v2  = in2[__float_as_int(e1.x) * 32 + lane];
        float2 v3  = in2[__float_as_int(e1.z) * 32 + lane];
        float2 v4  = in2[__float_as_int(e2.x) * 32 + lane];
        float2 v5  = in2[__float_as_int(e2.z) * 32 + lane];
        float2 v6  = in2[__float_as_int(e3.x) * 32 + lane];
        float2 v7  = in2[__float_as_int(e3.z) * 32 + lane];
        float2 v8  = in2[__float_as_int(e4.x) * 32 + lane];
        float2 v9  = in2[__float_as_int(e4.z) * 32 + lane];
        float2 v10 = in2[__float_as_int(e5.x) * 32 + lane];
        float2 v11 = in2[__float_as_int(e5.z) * 32 + lane];
        float2 v12 = in2[__float_as_int(e6.x) * 32 + lane];
        float2 v13 = in2[__float_as_int(e6.z) * 32 + lane];
        float2 v14 = in2[__float_as_int(e7.x) * 32 + lane];
        float2 v15 = in2[__float_as_int(e7.z) * 32 + lane];
        acc.x = fmaf(e0.y, v0.x,  acc.x);  acc.y = fmaf(e0.y, v0.y,  acc.y);
        acc.x = fmaf(e0.w, v1.x,  acc.x);  acc.y = fmaf(e0.w, v1.y,  acc.y);
        acc.x = fmaf(e1.y, v2.x,  acc.x);  acc.y = fmaf(e1.y, v2.y,  acc.y);
        acc.x = fmaf(e1.w, v3.x,  acc.x);  acc.y = fmaf(e1.w, v3.y,  acc.y);
        acc.x = fmaf(e2.y, v4.x,  acc.x);  acc.y = fmaf(e2.y, v4.y,  acc.y);
        acc.x = fmaf(e2.w, v5.x,  acc.x);  acc.y = fmaf(e2.w, v5.y,  acc.y);
        acc.x = fmaf(e3.y, v6.x,  acc.x);  acc.y = fmaf(e3.y, v6.y,  acc.y);
        acc.x = fmaf(e3.w, v7.x,  acc.x);  acc.y = fmaf(e3.w, v7.y,  acc.y);
        acc.x = fmaf(e4.y, v8.x,  acc.x);  acc.y = fmaf(e4.y, v8.y,  acc.y);
        acc.x = fmaf(e4.w, v9.x,  acc.x);  acc.y = fmaf(e4.w, v9.y,  acc.y);
        acc.x = fmaf(e5.y, v10.x, acc.x);  acc.y = fmaf(e5.y, v10.y, acc.y);
        acc.x = fmaf(e5.w, v11.x, acc.x);  acc.y = fmaf(e5.w, v11.y, acc.y);
        acc.x = fmaf(e6.y, v12.x, acc.x);  acc.y = fmaf(e6.y, v12.y, acc.y);
        acc.x = fmaf(e6.w, v13.x, acc.x);  acc.y = fmaf(e6.w, v13.y, acc.y);
        acc.x = fmaf(e7.y, v14.x, acc.x);  acc.y = fmaf(e7.y, v14.y, acc.y);
        acc.x = fmaf(e7.w, v15.x, acc.x);  acc.y = fmaf(e7.w, v15.y, acc.y);
    }

    float2 res;
    if (LAYER == 1) {
        float z0 = 0.f, z1 = 0.f;
        #pragma unroll
        for (int j = 0; j < HH; j++) {
            z0 += fmaxf(fmaf(acc.x, sW1[j], sB1[j]), 0.f) * sW2[j];
            z1 += fmaxf(fmaf(acc.y, sW1[j], sB1[j]), 0.f) * sW2[j];
        }
        res = make_float2(z0, z1);
    } else {
        float bb = __ldg(b2);
        res = make_float2(acc.x + bb, acc.y + bb);
    }
    ou2[row * 32 + lane] = res;
}

// ---- K_F: transpose out (N,G)->(G,N) fused with mask merge (mask is int32) ----
__global__ void k_out(const float* __restrict__ x, const int* __restrict__ mask,
                      float* __restrict__ out) {
    __shared__ float t[32][33];
    int n0 = blockIdx.x * 32, g0 = blockIdx.y * 32;
    int tx = threadIdx.x, ty = threadIdx.y;
    int n = n0 + ty, g = g0 + tx;
    if (n < NN) t[ty][tx] = d_ot[n * GG + g];
    __syncthreads();
    n = n0 + tx; g = g0 + ty;
    if (n < NN) {
        int idx = g * NN + n;
        out[idx] = mask[idx] ? x[idx] : t[tx][ty];
    }
}

extern "C" void kernel_launch(void* const* d_in, const int* in_sizes, int n_in,
                              void* d_out, int out_size) {
    const float* x    = (const float*)d_in[0];
    const int*   mask = (const int*)d_in[1];      // jax bool -> int32 on the wire
    const int*   ei   = (const int*)d_in[2];
    const float* w    = (const float*)d_in[3];
    const float* W1   = (const float*)d_in[4];
    const float* b1   = (const float*)d_in[5];
    const float* W2   = (const float*)d_in[6];
    const float* b2   = (const float*)d_in[7];
    float*       out  = (float*)d_out;

    dim3 tb(32, 32);
    dim3 tg((NN + 31) / 32, GG / 32);
    k_prep<<<tg, tb>>>(x);
    k_build<<<(EE / 2 + 255) / 256, 256>>>(ei, w);
    k_norm<<<(NN + 3) / 4, 256>>>();
    k_spmv<1><<<NN / 8, 256>>>(W1, b1, W2, b2);
    k_spmv<2><<<NN / 8, 256>>>(W1, b1, W2, b2);
    k_out<<<tg, tb>>>(x, mask, out);
}